// round 3
// baseline (speedup 1.0000x reference)
#include <cuda_runtime.h>
#include <cstdint>

typedef unsigned long long ull;

// ---------------------------------------------------------------------------
// LSTM autoencoder: 4 layers, B=64, T=1024, H in {256,128,256,256}.
//   1) sgemm_bias: zx = x@W + b   (fp32 GEMM using packed fma.rn.f32x2)
//   2) lstm_rec:   persistent 128-CTA kernel, 8 batch groups x 16 col CTAs,
//      release/acquire flag sync per step; packed-f32x2 recurrence matmul.
// ---------------------------------------------------------------------------

#define T_STEPS 1024
#define BATCH   64

__device__ float g_zx[67108864];           // [B*T][4*256] max
__device__ float g_bufA[16777216];         // [B][T][256]
__device__ float g_bufB[8388608];          // [B][T][128]
__device__ int   g_flags[4 * 8 * T_STEPS]; // [layer][G][T]

// -------------------- primitives -------------------------------------------
__device__ __forceinline__ int ld_acquire_gpu(const int* p) {
    int v;
    asm volatile("ld.acquire.gpu.global.s32 %0, [%1];" : "=r"(v) : "l"(p) : "memory");
    return v;
}
__device__ __forceinline__ void red_release_gpu_add(int* p, int v) {
    asm volatile("red.release.gpu.global.add.s32 [%0], %1;" :: "l"(p), "r"(v) : "memory");
}
__device__ __forceinline__ ull pack2(float x, float y) {
    ull r;
    asm("mov.b64 %0, {%1, %2};" : "=l"(r) : "f"(x), "f"(y));
    return r;
}
__device__ __forceinline__ ull ffma2(ull a, ull b, ull c) {
    ull d;
    asm("fma.rn.f32x2 %0, %1, %2, %3;" : "=l"(d) : "l"(a), "l"(b), "l"(c));
    return d;
}
__device__ __forceinline__ float sum2(ull a) {
    float x, y;
    asm("mov.b64 {%0, %1}, %2;" : "=f"(x), "=f"(y) : "l"(a));
    return x + y;
}

// ---------------------------------------------------------------------------
// GEMM: C[m][n] = sum_k A[m][k]*B[k][n] + bias[n]
// BM=128, BN=64, BK=16, 256 threads. Accumulators packed over k (f32x2):
// acc halves hold even-k / odd-k partial sums, summed in the epilogue.
// Requires M%128==0, N%64==0, K%16==0 (true for all 4 layers).
// ---------------------------------------------------------------------------
__global__ __launch_bounds__(256, 2) void sgemm_bias(
    const float* __restrict__ A, const float* __restrict__ B,
    const float* __restrict__ bias, float* __restrict__ C,
    int M, int N, int K)
{
    const int BM = 128, BN = 64, BK = 16, K2T = BK / 2;
    __shared__ ull As2[K2T][BM];   // 8 KB  (k-pair major)
    __shared__ ull Bs2[K2T][BN];   // 4 KB

    int tid = threadIdx.x;
    int bm  = blockIdx.y * BM;
    int bn  = blockIdx.x * BN;

    // compute mapping: rows rg*4..+3, cols cgp + 8*j (j<8)
    int rg  = tid >> 3;      // 0..31
    int cgp = tid & 7;       // 0..7

    ull acc[4][8];
#pragma unroll
    for (int i = 0; i < 4; i++)
#pragma unroll
        for (int j = 0; j < 8; j++) acc[i][j] = 0ull;

    // load mapping
    int aRow = tid >> 1;           // 0..127
    int aCol = (tid & 1) * 8;      // 0 or 8
    int bRow = tid >> 4;           // 0..15
    int bCol = (tid & 15) * 4;     // 0..60
    int bk2  = bRow >> 1;
    int bpar = bRow & 1;

    const float* Ap = A + (size_t)(bm + aRow) * K;

    for (int k0 = 0; k0 < K; k0 += BK) {
        float4 av0 = *(const float4*)&Ap[k0 + aCol];
        float4 av1 = *(const float4*)&Ap[k0 + aCol + 4];
        float4 bv  = *(const float4*)&B[(size_t)(k0 + bRow) * N + bn + bCol];
        __syncthreads();
        int ac2 = aCol >> 1;
        As2[ac2 + 0][aRow] = pack2(av0.x, av0.y);
        As2[ac2 + 1][aRow] = pack2(av0.z, av0.w);
        As2[ac2 + 2][aRow] = pack2(av1.x, av1.y);
        As2[ac2 + 3][aRow] = pack2(av1.z, av1.w);
        float* bs = (float*)&Bs2[bk2][0];
        bs[(bCol + 0) * 2 + bpar] = bv.x;
        bs[(bCol + 1) * 2 + bpar] = bv.y;
        bs[(bCol + 2) * 2 + bpar] = bv.z;
        bs[(bCol + 3) * 2 + bpar] = bv.w;
        __syncthreads();
#pragma unroll
        for (int k2 = 0; k2 < K2T; k2++) {
            ull a[4], b[8];
            *(ulonglong2*)&a[0] = *(const ulonglong2*)&As2[k2][rg * 4];
            *(ulonglong2*)&a[2] = *(const ulonglong2*)&As2[k2][rg * 4 + 2];
#pragma unroll
            for (int j = 0; j < 8; j++) b[j] = Bs2[k2][cgp + 8 * j];
#pragma unroll
            for (int i = 0; i < 4; i++)
#pragma unroll
                for (int j = 0; j < 8; j++)
                    acc[i][j] = ffma2(a[i], b[j], acc[i][j]);
        }
    }

#pragma unroll
    for (int i = 0; i < 4; i++) {
        size_t row = (size_t)(bm + rg * 4 + i);
#pragma unroll
        for (int j = 0; j < 8; j++) {
            int col = bn + cgp + 8 * j;
            C[row * N + col] = sum2(acc[i][j]) + __ldg(&bias[col]);
        }
    }
}

// ---------------------------------------------------------------------------
// Persistent LSTM recurrence.
//   grid = 128 CTAs: blockIdx.x = g*16 + cb. Group g = 8 batch rows; column
//   CTA cb owns NH = H/16 h-columns (4 gate cols each). U packed over k-pairs
//   in smem; matmul uses fma.rn.f32x2 (even/odd-k halves, summed at zp store).
// ---------------------------------------------------------------------------
template <int H>
__global__ __launch_bounds__(256) void lstm_rec(
    const float* __restrict__ zx,   // [B][T][4H]
    const float* __restrict__ U,    // [H][4H]
    float* __restrict__ out,        // [B][T][H]  (also h exchange buffer)
    int* __restrict__ flags)        // [G][T]
{
    constexpr int N4   = 4 * H;
    constexpr int Bg   = 8;
    constexpr int Pc   = 16;
    constexpr int NH   = H / Pc;      // 16 / 8
    constexpr int NCZ  = 4 * NH;      // 64 / 32
    constexpr int K2   = H / 2;       // 128 / 64
    constexpr int KS   = 256 / NCZ;   // 4 / 8   (split-K slices)
    constexpr int K2S  = K2 / KS;     // 32 / 8  (k-pairs per slice)
    constexpr int HCG  = NCZ / 2;     // 32 / 16
    constexpr int NRED = Bg * NH;     // 128 / 64

    extern __shared__ char smraw[];
    ull*   U2  = (ull*)smraw;              // [K2][NCZ] packed k-pairs
    float* h_s = (float*)(U2 + K2 * NCZ);  // [Bg][H]
    float* zp  = h_s + Bg * H;             // [KS][Bg][NCZ]
    const ull* h2 = (const ull*)h_s;       // [Bg][K2]

    int tid = threadIdx.x;
    int g   = blockIdx.x >> 4;
    int cb  = blockIdx.x & 15;
    int jb  = cb * NH;

    // Pack U slice: U2[k2][c] = (U[2k2][gcol], U[2k2+1][gcol]),
    // gcol = gi*H + jb + j, c = gi*NH + j.
    for (int idx = tid; idx < K2 * NCZ; idx += 256) {
        int k2 = idx / NCZ;
        int c  = idx % NCZ;
        int gi = c / NH;
        int j  = c % NH;
        int gcol = gi * H + jb + j;
        U2[idx] = pack2(U[(size_t)(2 * k2) * N4 + gcol],
                        U[(size_t)(2 * k2 + 1) * N4 + gcol]);
    }

    // matmul identity: slice s, rows rg*4..+3, cols cg and cg+HCG
    int s   = tid / NCZ;
    int rem = tid % NCZ;
    int rg  = rem / HCG;
    int cg  = rem % HCG;

    // reduce identity (tid < NRED)
    int rr = tid / NH;
    int jj = tid % NH;
    int bglob = g * Bg + rr;
    float creg = 0.f;

    int* flagrd = flags + g * T_STEPS;
    __syncthreads();

    for (int t = 0; t < T_STEPS; t++) {
        // Prefetch zx for this step (independent of h availability).
        float zx0 = 0.f, zx1 = 0.f, zx2 = 0.f, zx3 = 0.f;
        if (tid < NRED) {
            size_t base = ((size_t)bglob * T_STEPS + t) * N4 + jb + jj;
            zx0 = zx[base + 0 * (size_t)H];
            zx1 = zx[base + 1 * (size_t)H];
            zx2 = zx[base + 2 * (size_t)H];
            zx3 = zx[base + 3 * (size_t)H];
        }

        float z0 = 0.f, z1 = 0.f, z2 = 0.f, z3 = 0.f;
        if (t > 0) {
            if (tid == 0) {
                while (ld_acquire_gpu(&flagrd[t - 1]) < Pc) { }
            }
            __syncthreads();                                  // B1

            // h_{t-1}[Bg][H] from global
            for (int i4 = tid; i4 < (Bg * H) / 4; i4 += 256) {
                int idx = i4 * 4;
                int r = idx / H, k = idx % H;
                *(float4*)&h_s[idx] =
                    *(const float4*)&out[((size_t)(g * Bg + r) * T_STEPS + (t - 1)) * H + k];
            }
            __syncthreads();                                  // B2

            // packed matmul: z[8][NCZ] += h[8][H] @ Uslice[H][NCZ]
            ull acc0[4], acc1[4];
#pragma unroll
            for (int i = 0; i < 4; i++) { acc0[i] = 0ull; acc1[i] = 0ull; }
            int k2b = s * K2S;
#pragma unroll 4
            for (int kk = 0; kk < K2S; kk++) {
                int k2 = k2b + kk;
                ull u0 = U2[k2 * NCZ + cg];
                ull u1 = U2[k2 * NCZ + cg + HCG];
#pragma unroll
                for (int i = 0; i < 4; i++) {
                    ull hv = h2[(rg * 4 + i) * K2 + k2];
                    acc0[i] = ffma2(hv, u0, acc0[i]);
                    acc1[i] = ffma2(hv, u1, acc1[i]);
                }
            }
#pragma unroll
            for (int i = 0; i < 4; i++) {
                zp[(s * Bg + rg * 4 + i) * NCZ + cg]       = sum2(acc0[i]);
                zp[(s * Bg + rg * 4 + i) * NCZ + cg + HCG] = sum2(acc1[i]);
            }
            __syncthreads();                                  // B3

            if (tid < NRED) {
#pragma unroll
                for (int s2 = 0; s2 < KS; s2++) {
                    const float* zr = &zp[(s2 * Bg + rr) * NCZ];
                    z0 += zr[0 * NH + jj];
                    z1 += zr[1 * NH + jj];
                    z2 += zr[2 * NH + jj];
                    z3 += zr[3 * NH + jj];
                }
            }
        }

        // Gates + state update + publish h_t.
        if (tid < NRED) {
            float zi = zx0 + z0, zf = zx1 + z1, zg = zx2 + z2, zo = zx3 + z3;
            float si = 1.f / (1.f + __expf(-zi));
            float sf = 1.f / (1.f + __expf(-zf));
            float so = 1.f / (1.f + __expf(-zo));
            float gg = zg > 0.f ? zg : 0.f;
            creg = sf * creg + si * gg;
            float cr = creg > 0.f ? creg : 0.f;
            out[((size_t)bglob * T_STEPS + t) * H + jb + jj] = so * cr;
        }
        __syncthreads();                                      // B4
        if (tid == 0) red_release_gpu_add(&flags[g * T_STEPS + t], 1);
    }
}

// ---------------------------------------------------------------------------
extern "C" void kernel_launch(void* const* d_in, const int* in_sizes, int n_in,
                              void* d_out, int out_size)
{
    const float* x  = (const float*)d_in[0];
    const float* W1 = (const float*)d_in[1];
    const float* U1 = (const float*)d_in[2];
    const float* b1 = (const float*)d_in[3];
    const float* W2 = (const float*)d_in[4];
    const float* U2 = (const float*)d_in[5];
    const float* b2 = (const float*)d_in[6];
    const float* W3 = (const float*)d_in[7];
    const float* U3 = (const float*)d_in[8];
    const float* b3 = (const float*)d_in[9];
    const float* W4 = (const float*)d_in[10];
    const float* U4 = (const float*)d_in[11];
    const float* b4 = (const float*)d_in[12];
    float* out = (float*)d_out;

    void *zx_p, *bufA_p, *bufB_p, *flags_p;
    cudaGetSymbolAddress(&zx_p,    g_zx);
    cudaGetSymbolAddress(&bufA_p,  g_bufA);
    cudaGetSymbolAddress(&bufB_p,  g_bufB);
    cudaGetSymbolAddress(&flags_p, g_flags);
    float* zx    = (float*)zx_p;
    float* bufA  = (float*)bufA_p;
    float* bufB  = (float*)bufB_p;
    int*   flags = (int*)flags_p;

    const int M = BATCH * T_STEPS;  // 65536

    // dyn smem: U2 (K2*NCZ*8) + h (Bg*H*4) + zp (KS*Bg*NCZ*4)
    const int SMEM256 = 128 * 64 * 8 + 8 * 256 * 4 + 4 * 8 * 64 * 4;   // 81920 B
    const int SMEM128 = 64 * 32 * 8 + 8 * 128 * 4 + 8 * 8 * 32 * 4;    // 28672 B
    cudaFuncSetAttribute((const void*)lstm_rec<256>,
                         cudaFuncAttributeMaxDynamicSharedMemorySize, SMEM256);
    cudaFuncSetAttribute((const void*)lstm_rec<128>,
                         cudaFuncAttributeMaxDynamicSharedMemorySize, SMEM128);

    cudaMemsetAsync(flags, 0, 4 * 8 * T_STEPS * sizeof(int));

    // ---- Layer 1: F=256 -> H=256 ----
    sgemm_bias<<<dim3(1024 / 64, M / 128), 256>>>(x, W1, b1, zx, M, 1024, 256);
    lstm_rec<256><<<128, 256, SMEM256>>>(zx, U1, bufA, flags + 0 * 8 * T_STEPS);

    // ---- Layer 2: F=256 -> H=128 ----
    sgemm_bias<<<dim3(512 / 64, M / 128), 256>>>(bufA, W2, b2, zx, M, 512, 256);
    lstm_rec<128><<<128, 256, SMEM128>>>(zx, U2, bufB, flags + 1 * 8 * T_STEPS);

    // ---- Layer 3: F=128 -> H=256 ----
    sgemm_bias<<<dim3(1024 / 64, M / 128), 256>>>(bufB, W3, b3, zx, M, 1024, 128);
    lstm_rec<256><<<128, 256, SMEM256>>>(zx, U3, bufA, flags + 2 * 8 * T_STEPS);

    // ---- Layer 4: F=256 -> H=256 ----
    sgemm_bias<<<dim3(1024 / 64, M / 128), 256>>>(bufA, W4, b4, zx, M, 1024, 256);
    lstm_rec<256><<<128, 256, SMEM256>>>(zx, U4, out, flags + 3 * 8 * T_STEPS);
}

// round 4
// speedup vs baseline: 1.2097x; 1.2097x over previous
#include <cuda_runtime.h>
#include <cstdint>

typedef unsigned long long ull;

// ---------------------------------------------------------------------------
// LSTM autoencoder: 4 layers, B=64, T=1024, H in {256,128,256,256}.
//   1) sgemm_bias: zx = x@W + b   (fp32 128x128x8 GEMM, FMA-bound)
//   2) lstm_rec:   persistent 128-CTA kernel, 8 batch groups x 16 col CTAs.
//      U slice lives in REGISTERS (constant across steps); h broadcast via
//      smem; release/acquire flag sync per step through L2.
// ---------------------------------------------------------------------------

#define T_STEPS 1024
#define BATCH   64

__device__ float g_zx[67108864];           // [B*T][4*256] max
__device__ float g_bufA[16777216];         // [B][T][256]
__device__ float g_bufB[8388608];          // [B][T][128]
__device__ int   g_flags[4 * 8 * T_STEPS]; // [layer][G][T]

// -------------------- primitives -------------------------------------------
__device__ __forceinline__ int ld_acquire_gpu(const int* p) {
    int v;
    asm volatile("ld.acquire.gpu.global.s32 %0, [%1];" : "=r"(v) : "l"(p) : "memory");
    return v;
}
__device__ __forceinline__ void red_release_gpu_add(int* p, int v) {
    asm volatile("red.release.gpu.global.add.s32 [%0], %1;" :: "l"(p), "r"(v) : "memory");
}
__device__ __forceinline__ ull pack2(float x, float y) {
    ull r;
    asm("mov.b64 %0, {%1, %2};" : "=l"(r) : "f"(x), "f"(y));
    return r;
}
__device__ __forceinline__ ull ffma2(ull a, ull b, ull c) {
    ull d;
    asm("fma.rn.f32x2 %0, %1, %2, %3;" : "=l"(d) : "l"(a), "l"(b), "l"(c));
    return d;
}
__device__ __forceinline__ float sum2(ull a) {
    float x, y;
    asm("mov.b64 {%0, %1}, %2;" : "=f"(x), "=f"(y) : "l"(a));
    return x + y;
}

// ---------------------------------------------------------------------------
// GEMM (round-2 proven version): C[m][n] = sum_k A[m][k]*B[k][n] + bias[n]
// BM=128, BN=128, BK=8, 256 threads, 8x8 microtile. ~1 B smem per FMA.
// ---------------------------------------------------------------------------
__global__ __launch_bounds__(256) void sgemm_bias(
    const float* __restrict__ A, const float* __restrict__ B,
    const float* __restrict__ bias, float* __restrict__ C,
    int M, int N, int K)
{
    const int BM = 128, BN = 128, BK = 8;
    __shared__ float As[BK][BM];
    __shared__ float Bs[BK][BN];

    int tid = threadIdx.x;
    int bm  = blockIdx.y * BM;
    int bn  = blockIdx.x * BN;
    int tx  = tid & 15;
    int ty  = tid >> 4;

    float acc[8][8];
#pragma unroll
    for (int i = 0; i < 8; i++)
#pragma unroll
        for (int j = 0; j < 8; j++) acc[i][j] = 0.f;

    int aRow = tid >> 1;
    int aCol = (tid & 1) * 4;
    int bRow = tid >> 5;
    int bCol = (tid & 31) * 4;

    const float* Aptr = A + (size_t)(bm + aRow) * K;

    for (int k0 = 0; k0 < K; k0 += BK) {
        float4 av = *(const float4*)&Aptr[k0 + aCol];
        float4 bv = *(const float4*)&B[(size_t)(k0 + bRow) * N + bn + bCol];
        __syncthreads();
        As[aCol + 0][aRow] = av.x;
        As[aCol + 1][aRow] = av.y;
        As[aCol + 2][aRow] = av.z;
        As[aCol + 3][aRow] = av.w;
        *(float4*)&Bs[bRow][bCol] = bv;
        __syncthreads();
#pragma unroll
        for (int kk = 0; kk < BK; kk++) {
            float a[8], b[8];
            *(float4*)&a[0] = *(const float4*)&As[kk][ty * 8];
            *(float4*)&a[4] = *(const float4*)&As[kk][ty * 8 + 4];
            *(float4*)&b[0] = *(const float4*)&Bs[kk][tx * 8];
            *(float4*)&b[4] = *(const float4*)&Bs[kk][tx * 8 + 4];
#pragma unroll
            for (int i = 0; i < 8; i++)
#pragma unroll
                for (int j = 0; j < 8; j++)
                    acc[i][j] += a[i] * b[j];
        }
    }

#pragma unroll
    for (int i = 0; i < 8; i++) {
        size_t row = (size_t)(bm + ty * 8 + i);
#pragma unroll
        for (int j = 0; j < 8; j += 4) {
            int col = bn + tx * 8 + j;
            float4 o;
            o.x = acc[i][j + 0] + bias[col + 0];
            o.y = acc[i][j + 1] + bias[col + 1];
            o.z = acc[i][j + 2] + bias[col + 2];
            o.w = acc[i][j + 3] + bias[col + 3];
            *(float4*)&C[row * N + col] = o;
        }
    }
}

// ---------------------------------------------------------------------------
// Persistent LSTM recurrence, U-in-registers.
//   grid = 128 CTAs: blockIdx.x = g*16 + cb. Group g = 8 batch rows; CTA cb
//   owns NH = H/16 h-columns (NCZ = 4*NH gate columns).
//   Thread decomposition (256 threads): tid -> (s, cb2, rs):
//     s   in [0,SL)  : k-slice, KP = K2/SL k-pairs
//     cb2 in [0,CB)  : column block of CW=4 gate columns
//     rs  in [0,RS)  : row split, RT = 8/RS rows per thread
//   Each thread permanently holds Ureg[KP][CW] (32 ull = 64 regs).
//   Per step: load h (smem, warp-broadcast), FFMA2 outer product, zp split-K
//   reduce in smem, gates, publish h via the layer output buffer in L2.
// ---------------------------------------------------------------------------
template <int H, int SL, int KP, int CB, int RS>
__global__ __launch_bounds__(256, 1) void lstm_rec(
    const float* __restrict__ zx,   // [B][T][4H]
    const float* __restrict__ U,    // [H][4H]
    float* __restrict__ out,        // [B][T][H]  (also h exchange buffer)
    int* __restrict__ flags)        // [G][T]
{
    constexpr int N4   = 4 * H;
    constexpr int Bg   = 8;
    constexpr int Pc   = 16;
    constexpr int NH   = H / Pc;
    constexpr int NCZ  = 4 * NH;
    constexpr int K2   = H / 2;
    constexpr int CW   = 4;
    constexpr int RT   = Bg / RS;
    constexpr int NRED = Bg * NH;
    static_assert(SL * KP == K2, "k split");
    static_assert(CB * CW == NCZ, "col split");
    static_assert(SL * CB * RS == 256, "thread count");

    __shared__ ull   h2[Bg * K2];           // h_{t-1} as packed k-pairs
    __shared__ float zp[SL * Bg * NCZ];     // split-K partials
    float* h_s = (float*)h2;                // alias: [Bg][H] floats

    int tid = threadIdx.x;
    int g   = blockIdx.x >> 4;
    int cb  = blockIdx.x & 15;
    int jb  = cb * NH;

    // thread decomposition
    int s   = tid / (CB * RS);
    int rem = tid % (CB * RS);
    int cb2 = rem / RS;
    int rs  = rem % RS;

    // Load U slice into registers (one-time, from global).
    ull Ureg[KP][CW];
#pragma unroll
    for (int kk = 0; kk < KP; kk++) {
#pragma unroll
        for (int cw = 0; cw < CW; cw++) {
            int c    = cb2 * CW + cw;
            int gi   = c / NH;
            int j    = c % NH;
            int gcol = gi * H + jb + j;
            int k2   = s * KP + kk;
            Ureg[kk][cw] = pack2(__ldg(&U[(size_t)(2 * k2) * N4 + gcol]),
                                 __ldg(&U[(size_t)(2 * k2 + 1) * N4 + gcol]));
        }
    }

    // reduce identity (tid < NRED)
    int rr = tid / NH;
    int jj = tid % NH;
    int bglob = g * Bg + rr;
    float creg = 0.f;

    int* flagrd = flags + g * T_STEPS;
    __syncthreads();

    for (int t = 0; t < T_STEPS; t++) {
        // Prefetch zx (independent of h availability; in flight during spin).
        float zx0 = 0.f, zx1 = 0.f, zx2 = 0.f, zx3 = 0.f;
        if (tid < NRED) {
            size_t base = ((size_t)bglob * T_STEPS + t) * N4 + jb + jj;
            zx0 = zx[base + 0 * (size_t)H];
            zx1 = zx[base + 1 * (size_t)H];
            zx2 = zx[base + 2 * (size_t)H];
            zx3 = zx[base + 3 * (size_t)H];
        }

        float z0 = 0.f, z1 = 0.f, z2 = 0.f, z3 = 0.f;
        if (t > 0) {
            if (tid == 0) {
                while (ld_acquire_gpu(&flagrd[t - 1]) < Pc) { }
            }
            __syncthreads();                                  // B1

            // h_{t-1}[Bg][H] from global into smem.
            for (int i4 = tid; i4 < (Bg * H) / 4; i4 += 256) {
                int idx = i4 * 4;
                int r = idx / H, k = idx % H;
                *(float4*)&h_s[idx] =
                    *(const float4*)&out[((size_t)(g * Bg + r) * T_STEPS + (t - 1)) * H + k];
            }
            __syncthreads();                                  // B2

            // Outer-product matmul: only h comes from smem (warp-broadcast).
            ull acc[RT][CW];
#pragma unroll
            for (int i = 0; i < RT; i++)
#pragma unroll
                for (int cw = 0; cw < CW; cw++) acc[i][cw] = 0ull;

#pragma unroll
            for (int kk = 0; kk < KP; kk++) {
                int k2 = s * KP + kk;
                ull hv[RT];
#pragma unroll
                for (int i = 0; i < RT; i++)
                    hv[i] = h2[(rs * RT + i) * K2 + k2];
#pragma unroll
                for (int i = 0; i < RT; i++)
#pragma unroll
                    for (int cw = 0; cw < CW; cw++)
                        acc[i][cw] = ffma2(hv[i], Ureg[kk][cw], acc[i][cw]);
            }
#pragma unroll
            for (int i = 0; i < RT; i++) {
                float4 v;
                v.x = sum2(acc[i][0]);
                v.y = sum2(acc[i][1]);
                v.z = sum2(acc[i][2]);
                v.w = sum2(acc[i][3]);
                *(float4*)&zp[(s * Bg + rs * RT + i) * NCZ + cb2 * CW] = v;
            }
            __syncthreads();                                  // B3

            if (tid < NRED) {
#pragma unroll
                for (int s2 = 0; s2 < SL; s2++) {
                    const float* zr = &zp[(s2 * Bg + rr) * NCZ];
                    z0 += zr[0 * NH + jj];
                    z1 += zr[1 * NH + jj];
                    z2 += zr[2 * NH + jj];
                    z3 += zr[3 * NH + jj];
                }
            }
        }

        // Gates + state update + publish h_t.
        if (tid < NRED) {
            float zi = zx0 + z0, zf = zx1 + z1, zg = zx2 + z2, zo = zx3 + z3;
            float si = 1.f / (1.f + __expf(-zi));
            float sf = 1.f / (1.f + __expf(-zf));
            float so = 1.f / (1.f + __expf(-zo));
            float gg = zg > 0.f ? zg : 0.f;
            creg = sf * creg + si * gg;
            float cr = creg > 0.f ? creg : 0.f;
            out[((size_t)bglob * T_STEPS + t) * H + jb + jj] = so * cr;
        }
        __syncthreads();                                      // B4
        if (tid == 0) red_release_gpu_add(&flags[g * T_STEPS + t], 1);
    }
}

// ---------------------------------------------------------------------------
extern "C" void kernel_launch(void* const* d_in, const int* in_sizes, int n_in,
                              void* d_out, int out_size)
{
    const float* x  = (const float*)d_in[0];
    const float* W1 = (const float*)d_in[1];
    const float* U1 = (const float*)d_in[2];
    const float* b1 = (const float*)d_in[3];
    const float* W2 = (const float*)d_in[4];
    const float* U2 = (const float*)d_in[5];
    const float* b2 = (const float*)d_in[6];
    const float* W3 = (const float*)d_in[7];
    const float* U3 = (const float*)d_in[8];
    const float* b3 = (const float*)d_in[9];
    const float* W4 = (const float*)d_in[10];
    const float* U4 = (const float*)d_in[11];
    const float* b4 = (const float*)d_in[12];
    float* out = (float*)d_out;

    void *zx_p, *bufA_p, *bufB_p, *flags_p;
    cudaGetSymbolAddress(&zx_p,    g_zx);
    cudaGetSymbolAddress(&bufA_p,  g_bufA);
    cudaGetSymbolAddress(&bufB_p,  g_bufB);
    cudaGetSymbolAddress(&flags_p, g_flags);
    float* zx    = (float*)zx_p;
    float* bufA  = (float*)bufA_p;
    float* bufB  = (float*)bufB_p;
    int*   flags = (int*)flags_p;

    const int M = BATCH * T_STEPS;  // 65536

    cudaMemsetAsync(flags, 0, 4 * 8 * T_STEPS * sizeof(int));

    // lstm_rec configs: <H, SL, KP, CB, RS>
    //   H=256: SL=16 slices of KP=8 k-pairs, CB=16 col blocks, RS=1 (RT=8)
    //   H=128: SL=8  slices of KP=8 k-pairs, CB=8  col blocks, RS=4 (RT=2)

    // ---- Layer 1: F=256 -> H=256 ----
    sgemm_bias<<<dim3(1024 / 128, M / 128), 256>>>(x, W1, b1, zx, M, 1024, 256);
    lstm_rec<256, 16, 8, 16, 1><<<128, 256>>>(zx, U1, bufA, flags + 0 * 8 * T_STEPS);

    // ---- Layer 2: F=256 -> H=128 ----
    sgemm_bias<<<dim3(512 / 128, M / 128), 256>>>(bufA, W2, b2, zx, M, 512, 256);
    lstm_rec<128, 8, 8, 8, 4><<<128, 256>>>(zx, U2, bufB, flags + 1 * 8 * T_STEPS);

    // ---- Layer 3: F=128 -> H=256 ----
    sgemm_bias<<<dim3(1024 / 128, M / 128), 256>>>(bufB, W3, b3, zx, M, 1024, 128);
    lstm_rec<256, 16, 8, 16, 1><<<128, 256>>>(zx, U3, bufA, flags + 2 * 8 * T_STEPS);

    // ---- Layer 4: F=256 -> H=256 ----
    sgemm_bias<<<dim3(1024 / 128, M / 128), 256>>>(bufA, W4, b4, zx, M, 1024, 256);
    lstm_rec<256, 16, 8, 16, 1><<<128, 256>>>(zx, U4, out, flags + 3 * 8 * T_STEPS);
}

// round 6
// speedup vs baseline: 1.3263x; 1.0964x over previous
#include <cuda_runtime.h>
#include <cuda_bf16.h>
#include <cstdint>

typedef unsigned long long ull;

// ---------------------------------------------------------------------------
// LSTM autoencoder: 4 layers, B=64, T=1024, H in {256,128,256,256}.
//   zx GEMMs: mma.sync bf16 split-precision (hi/lo, 3 products, fp32 accum)
//   recurrence: persistent 128-CTA kernel (R4 design, U in registers)
// ---------------------------------------------------------------------------

#define T_STEPS 1024
#define BATCH   64

__device__ float g_zx[67108864];           // [B*T][4*256] max
__device__ float g_bufA[16777216];         // [B][T][256]
__device__ float g_bufB[8388608];          // [B][T][128]
__device__ int   g_flags[4 * 8 * T_STEPS]; // [layer][G][T]
__device__ __nv_bfloat16 g_ahi[16777216];  // A hi  [M][K]
__device__ __nv_bfloat16 g_alo[16777216];  // A lo
__device__ __nv_bfloat16 g_wthi[262144];   // W^T hi [N][K]
__device__ __nv_bfloat16 g_wtlo[262144];   // W^T lo

// -------------------- scalar primitives ------------------------------------
__device__ __forceinline__ int ld_acquire_gpu(const int* p) {
    int v;
    asm volatile("ld.acquire.gpu.global.s32 %0, [%1];" : "=r"(v) : "l"(p) : "memory");
    return v;
}
__device__ __forceinline__ void red_release_gpu_add(int* p, int v) {
    asm volatile("red.release.gpu.global.add.s32 [%0], %1;" :: "l"(p), "r"(v) : "memory");
}
__device__ __forceinline__ ull pack2(float x, float y) {
    ull r; asm("mov.b64 %0, {%1, %2};" : "=l"(r) : "f"(x), "f"(y)); return r;
}
__device__ __forceinline__ ull ffma2(ull a, ull b, ull c) {
    ull d; asm("fma.rn.f32x2 %0, %1, %2, %3;" : "=l"(d) : "l"(a), "l"(b), "l"(c)); return d;
}
__device__ __forceinline__ float sum2(ull a) {
    float x, y; asm("mov.b64 {%0, %1}, %2;" : "=f"(x), "=f"(y) : "l"(a)); return x + y;
}
__device__ __forceinline__ uint32_t smem_u32(const void* p) {
    uint32_t a;
    asm("{ .reg .u64 t; cvta.to.shared.u64 t, %1; cvt.u32.u64 %0, t; }" : "=r"(a) : "l"(p));
    return a;
}

// -------------------- tensor-core primitives (arch-portable) ----------------
__device__ __forceinline__ void ldmat4(uint32_t* r, uint32_t addr) {
    asm volatile("ldmatrix.sync.aligned.m8n8.x4.shared.b16 {%0,%1,%2,%3}, [%4];"
        : "=r"(r[0]), "=r"(r[1]), "=r"(r[2]), "=r"(r[3]) : "r"(addr));
}
__device__ __forceinline__ void mma16816(float* c, const uint32_t* a, const uint32_t* b) {
    asm volatile(
        "mma.sync.aligned.m16n8k16.row.col.f32.bf16.bf16.f32 "
        "{%0,%1,%2,%3}, {%4,%5,%6,%7}, {%8,%9}, {%0,%1,%2,%3};"
        : "+f"(c[0]), "+f"(c[1]), "+f"(c[2]), "+f"(c[3])
        : "r"(a[0]), "r"(a[1]), "r"(a[2]), "r"(a[3]), "r"(b[0]), "r"(b[1]));
}

// ---------------------------------------------------------------------------
// split_bf16: x -> (hi, lo) bf16, elementwise (vectorized x4)
// ---------------------------------------------------------------------------
__global__ __launch_bounds__(256) void split_bf16(
    const float* __restrict__ x, __nv_bfloat16* __restrict__ hi,
    __nv_bfloat16* __restrict__ lo, int n4)
{
    int i = blockIdx.x * 256 + threadIdx.x;
    if (i >= n4) return;
    float4 v = ((const float4*)x)[i];
    __nv_bfloat16 h0 = __float2bfloat16(v.x), h1 = __float2bfloat16(v.y);
    __nv_bfloat16 h2 = __float2bfloat16(v.z), h3 = __float2bfloat16(v.w);
    __nv_bfloat16 l0 = __float2bfloat16(v.x - __bfloat162float(h0));
    __nv_bfloat16 l1 = __float2bfloat16(v.y - __bfloat162float(h1));
    __nv_bfloat16 l2 = __float2bfloat16(v.z - __bfloat162float(h2));
    __nv_bfloat16 l3 = __float2bfloat16(v.w - __bfloat162float(h3));
    ((__nv_bfloat162*)hi)[2 * i + 0] = __nv_bfloat162(h0, h1);
    ((__nv_bfloat162*)hi)[2 * i + 1] = __nv_bfloat162(h2, h3);
    ((__nv_bfloat162*)lo)[2 * i + 0] = __nv_bfloat162(l0, l1);
    ((__nv_bfloat162*)lo)[2 * i + 1] = __nv_bfloat162(l2, l3);
}

// ---------------------------------------------------------------------------
// wsplit_t: W[K][N] fp32 -> Wt hi/lo [N][K] bf16 (transpose + split)
// ---------------------------------------------------------------------------
__global__ void wsplit_t(const float* __restrict__ W,
                         __nv_bfloat16* __restrict__ Th,
                         __nv_bfloat16* __restrict__ Tl, int K, int N)
{
    __shared__ float tile[32][33];
    int n0 = blockIdx.x * 32, k0 = blockIdx.y * 32;
    int tx = threadIdx.x, ty = threadIdx.y;
#pragma unroll
    for (int j = 0; j < 32; j += 8)
        tile[ty + j][tx] = W[(size_t)(k0 + ty + j) * N + n0 + tx];
    __syncthreads();
#pragma unroll
    for (int j = 0; j < 32; j += 8) {
        float v = tile[tx][ty + j];
        __nv_bfloat16 h = __float2bfloat16(v);
        __nv_bfloat16 l = __float2bfloat16(v - __bfloat162float(h));
        Th[(size_t)(n0 + ty + j) * K + k0 + tx] = h;
        Tl[(size_t)(n0 + ty + j) * K + k0 + tx] = l;
    }
}

// ---------------------------------------------------------------------------
// gemm_mma_split: C = Ahi@Bhi^T + Ahi@Blo^T + Alo@Bhi^T + bias
//   A*: [M][K] bf16, B*: [N][K] bf16 (K-major). Block 128x128, 8 warps (2x4),
//   warp tile 64x32 (4x4 m16n8k16 tiles), BK=32, padded smem rows (40 bf16),
//   ldmatrix fragment loads (conflict-free), bf16 HMMA, fp32 accum.
// ---------------------------------------------------------------------------
__global__ __launch_bounds__(256, 2) void gemm_mma_split(
    const __nv_bfloat16* __restrict__ Ahi, const __nv_bfloat16* __restrict__ Alo,
    const __nv_bfloat16* __restrict__ Bhi, const __nv_bfloat16* __restrict__ Blo,
    const float* __restrict__ bias, float* __restrict__ C,
    int M, int N, int K)
{
    __shared__ __nv_bfloat16 sAh[128][40], sAl[128][40], sBh[128][40], sBl[128][40];

    int tid = threadIdx.x;
    int wid = tid >> 5, lid = tid & 31;
    int wm = wid >> 2, wn = wid & 3;      // warp grid 2 x 4
    int g  = lid >> 2, tg = lid & 3;      // mma lane identity
    int lj = lid >> 3, lr = lid & 7;      // ldmatrix lane identity
    int bn = blockIdx.x * 128;
    int bm = blockIdx.y * 128;

    float acc[4][4][4];
#pragma unroll
    for (int mt = 0; mt < 4; mt++)
#pragma unroll
        for (int nt = 0; nt < 4; nt++)
#pragma unroll
            for (int q = 0; q < 4; q++) acc[mt][nt][q] = 0.f;

    uint32_t baseAh = smem_u32(&sAh[0][0]), baseAl = smem_u32(&sAl[0][0]);
    uint32_t baseBh = smem_u32(&sBh[0][0]), baseBl = smem_u32(&sBl[0][0]);

    // Precomputed ldmatrix lane offsets (bf16 units; *2 for bytes at use).
    // A (per mt, ks2): row = wm*64 + mt*16 + (lj&1)*8 + lr, col = ks2 + (lj>>1)*8
    // B (per ntp, ks2): row = wn*32 + ntp*16 + (lj>>1)*8 + lr, col = ks2 + (lj&1)*8
    int aRowL = wm * 64 + (lj & 1) * 8 + lr;
    int aColL = (lj >> 1) * 8;
    int bRowL = wn * 32 + (lj >> 1) * 8 + lr;
    int bColL = (lj & 1) * 8;

    for (int kc = 0; kc < K; kc += 32) {
        __syncthreads();
        // Load 4 tiles: 128 rows x 32 bf16 each, uint4 chunks.
        for (int i = tid; i < 512; i += 256) {
            int r = i >> 2, u = (i & 3) * 8;
            size_t ga = (size_t)(bm + r) * K + kc + u;
            size_t gb = (size_t)(bn + r) * K + kc + u;
            *(uint4*)&sAh[r][u] = *(const uint4*)&Ahi[ga];
            *(uint4*)&sAl[r][u] = *(const uint4*)&Alo[ga];
            *(uint4*)&sBh[r][u] = *(const uint4*)&Bhi[gb];
            *(uint4*)&sBl[r][u] = *(const uint4*)&Blo[gb];
        }
        __syncthreads();

#pragma unroll
        for (int ks2 = 0; ks2 < 32; ks2 += 16) {
            uint32_t bh[2][4], bl[2][4];
#pragma unroll
            for (int ntp = 0; ntp < 2; ntp++) {
                uint32_t off = (uint32_t)((bRowL + ntp * 16) * 40 + ks2 + bColL) * 2;
                ldmat4(bh[ntp], baseBh + off);
                ldmat4(bl[ntp], baseBl + off);
            }
#pragma unroll
            for (int mt = 0; mt < 4; mt++) {
                uint32_t ah[4], al[4];
                uint32_t off = (uint32_t)((aRowL + mt * 16) * 40 + ks2 + aColL) * 2;
                ldmat4(ah, baseAh + off);
                ldmat4(al, baseAl + off);
#pragma unroll
                for (int nt = 0; nt < 4; nt++) {
                    const uint32_t* pbh = &bh[nt >> 1][(nt & 1) * 2];
                    const uint32_t* pbl = &bl[nt >> 1][(nt & 1) * 2];
                    mma16816(acc[mt][nt], ah, pbh);
                    mma16816(acc[mt][nt], ah, pbl);
                    mma16816(acc[mt][nt], al, pbh);
                }
            }
        }
    }

    // Epilogue: direct global stores with bias.
#pragma unroll
    for (int mt = 0; mt < 4; mt++) {
#pragma unroll
        for (int nt = 0; nt < 4; nt++) {
            int row = bm + wm * 64 + mt * 16 + g;
            int col = bn + wn * 32 + nt * 8 + tg * 2;
            float b0 = __ldg(&bias[col]), b1 = __ldg(&bias[col + 1]);
            float2 v0 = make_float2(acc[mt][nt][0] + b0, acc[mt][nt][1] + b1);
            float2 v1 = make_float2(acc[mt][nt][2] + b0, acc[mt][nt][3] + b1);
            *(float2*)&C[(size_t)row * N + col]       = v0;
            *(float2*)&C[(size_t)(row + 8) * N + col] = v1;
        }
    }
}

// ---------------------------------------------------------------------------
// Persistent LSTM recurrence (R4 design, unchanged): U in registers.
// ---------------------------------------------------------------------------
template <int H, int SL, int KP, int CB, int RS>
__global__ __launch_bounds__(256, 1) void lstm_rec(
    const float* __restrict__ zx, const float* __restrict__ U,
    float* __restrict__ out, int* __restrict__ flags)
{
    constexpr int N4   = 4 * H;
    constexpr int Bg   = 8;
    constexpr int Pc   = 16;
    constexpr int NH   = H / Pc;
    constexpr int NCZ  = 4 * NH;
    constexpr int K2   = H / 2;
    constexpr int CW   = 4;
    constexpr int RT   = Bg / RS;
    constexpr int NRED = Bg * NH;
    static_assert(SL * KP == K2 && CB * CW == NCZ && SL * CB * RS == 256, "split");

    __shared__ ull   h2[Bg * K2];
    __shared__ float zp[SL * Bg * NCZ];
    float* h_s = (float*)h2;

    int tid = threadIdx.x;
    int g   = blockIdx.x >> 4;
    int cb  = blockIdx.x & 15;
    int jb  = cb * NH;

    int s   = tid / (CB * RS);
    int rem = tid % (CB * RS);
    int cb2 = rem / RS;
    int rs  = rem % RS;

    ull Ureg[KP][CW];
#pragma unroll
    for (int kk = 0; kk < KP; kk++)
#pragma unroll
        for (int cw = 0; cw < CW; cw++) {
            int c    = cb2 * CW + cw;
            int gi   = c / NH;
            int j    = c % NH;
            int gcol = gi * H + jb + j;
            int k2   = s * KP + kk;
            Ureg[kk][cw] = pack2(__ldg(&U[(size_t)(2 * k2) * N4 + gcol]),
                                 __ldg(&U[(size_t)(2 * k2 + 1) * N4 + gcol]));
        }

    int rr = tid / NH;
    int jj = tid % NH;
    int bglob = g * Bg + rr;
    float creg = 0.f;

    int* flagrd = flags + g * T_STEPS;
    __syncthreads();

    for (int t = 0; t < T_STEPS; t++) {
        float zx0 = 0.f, zx1 = 0.f, zx2 = 0.f, zx3 = 0.f;
        if (tid < NRED) {
            size_t basei = ((size_t)bglob * T_STEPS + t) * N4 + jb + jj;
            zx0 = zx[basei + 0 * (size_t)H];
            zx1 = zx[basei + 1 * (size_t)H];
            zx2 = zx[basei + 2 * (size_t)H];
            zx3 = zx[basei + 3 * (size_t)H];
        }

        float z0 = 0.f, z1 = 0.f, z2 = 0.f, z3 = 0.f;
        if (t > 0) {
            if (tid == 0) {
                while (ld_acquire_gpu(&flagrd[t - 1]) < Pc) { }
            }
            __syncthreads();

            for (int i4 = tid; i4 < (Bg * H) / 4; i4 += 256) {
                int idx = i4 * 4;
                int r = idx / H, k = idx % H;
                *(float4*)&h_s[idx] =
                    *(const float4*)&out[((size_t)(g * Bg + r) * T_STEPS + (t - 1)) * H + k];
            }
            __syncthreads();

            ull acc[RT][CW];
#pragma unroll
            for (int i = 0; i < RT; i++)
#pragma unroll
                for (int cw = 0; cw < CW; cw++) acc[i][cw] = 0ull;

#pragma unroll
            for (int kk = 0; kk < KP; kk++) {
                int k2 = s * KP + kk;
                ull hv[RT];
#pragma unroll
                for (int i = 0; i < RT; i++)
                    hv[i] = h2[(rs * RT + i) * K2 + k2];
#pragma unroll
                for (int i = 0; i < RT; i++)
#pragma unroll
                    for (int cw = 0; cw < CW; cw++)
                        acc[i][cw] = ffma2(hv[i], Ureg[kk][cw], acc[i][cw]);
            }
#pragma unroll
            for (int i = 0; i < RT; i++) {
                float4 v;
                v.x = sum2(acc[i][0]);
                v.y = sum2(acc[i][1]);
                v.z = sum2(acc[i][2]);
                v.w = sum2(acc[i][3]);
                *(float4*)&zp[(s * Bg + rs * RT + i) * NCZ + cb2 * CW] = v;
            }
            __syncthreads();

            if (tid < NRED) {
#pragma unroll
                for (int s2 = 0; s2 < SL; s2++) {
                    const float* zr = &zp[(s2 * Bg + rr) * NCZ];
                    z0 += zr[0 * NH + jj];
                    z1 += zr[1 * NH + jj];
                    z2 += zr[2 * NH + jj];
                    z3 += zr[3 * NH + jj];
                }
            }
        }

        if (tid < NRED) {
            float zi = zx0 + z0, zf = zx1 + z1, zg = zx2 + z2, zo = zx3 + z3;
            float si = 1.f / (1.f + __expf(-zi));
            float sf = 1.f / (1.f + __expf(-zf));
            float so = 1.f / (1.f + __expf(-zo));
            float gg = zg > 0.f ? zg : 0.f;
            creg = sf * creg + si * gg;
            float cr = creg > 0.f ? creg : 0.f;
            out[((size_t)bglob * T_STEPS + t) * H + jb + jj] = so * cr;
        }
        __syncthreads();
        if (tid == 0) red_release_gpu_add(&flags[g * T_STEPS + t], 1);
    }
}

// ---------------------------------------------------------------------------
extern "C" void kernel_launch(void* const* d_in, const int* in_sizes, int n_in,
                              void* d_out, int out_size)
{
    const float* x  = (const float*)d_in[0];
    const float* W1 = (const float*)d_in[1];
    const float* U1 = (const float*)d_in[2];
    const float* b1 = (const float*)d_in[3];
    const float* W2 = (const float*)d_in[4];
    const float* U2 = (const float*)d_in[5];
    const float* b2 = (const float*)d_in[6];
    const float* W3 = (const float*)d_in[7];
    const float* U3 = (const float*)d_in[8];
    const float* b3 = (const float*)d_in[9];
    const float* W4 = (const float*)d_in[10];
    const float* U4 = (const float*)d_in[11];
    const float* b4 = (const float*)d_in[12];
    float* out = (float*)d_out;

    void *p;
    cudaGetSymbolAddress(&p, g_zx);    float* zx    = (float*)p;
    cudaGetSymbolAddress(&p, g_bufA);  float* bufA  = (float*)p;
    cudaGetSymbolAddress(&p, g_bufB);  float* bufB  = (float*)p;
    cudaGetSymbolAddress(&p, g_flags); int*   flags = (int*)p;
    cudaGetSymbolAddress(&p, g_ahi);   __nv_bfloat16* ahi  = (__nv_bfloat16*)p;
    cudaGetSymbolAddress(&p, g_alo);   __nv_bfloat16* alo  = (__nv_bfloat16*)p;
    cudaGetSymbolAddress(&p, g_wthi);  __nv_bfloat16* wthi = (__nv_bfloat16*)p;
    cudaGetSymbolAddress(&p, g_wtlo);  __nv_bfloat16* wtlo = (__nv_bfloat16*)p;

    const int M = BATCH * T_STEPS;  // 65536

    cudaMemsetAsync(flags, 0, 4 * 8 * T_STEPS * sizeof(int));

    // ---- Layer 1: F=256 -> H=256 (N=1024, K=256) ----
    split_bf16<<<M * 256 / 4 / 256, 256>>>(x, ahi, alo, M * 256 / 4);
    wsplit_t<<<dim3(1024 / 32, 256 / 32), dim3(32, 8)>>>(W1, wthi, wtlo, 256, 1024);
    gemm_mma_split<<<dim3(8, M / 128), 256>>>(ahi, alo, wthi, wtlo, b1, zx, M, 1024, 256);
    lstm_rec<256, 16, 8, 16, 1><<<128, 256>>>(zx, U1, bufA, flags + 0 * 8 * T_STEPS);

    // ---- Layer 2: F=256 -> H=128 (N=512, K=256) ----
    split_bf16<<<M * 256 / 4 / 256, 256>>>(bufA, ahi, alo, M * 256 / 4);
    wsplit_t<<<dim3(512 / 32, 256 / 32), dim3(32, 8)>>>(W2, wthi, wtlo, 256, 512);
    gemm_mma_split<<<dim3(4, M / 128), 256>>>(ahi, alo, wthi, wtlo, b2, zx, M, 512, 256);
    lstm_rec<128, 8, 8, 8, 4><<<128, 256>>>(zx, U2, bufB, flags + 1 * 8 * T_STEPS);

    // ---- Layer 3: F=128 -> H=256 (N=1024, K=128) ----
    split_bf16<<<M * 128 / 4 / 256, 256>>>(bufB, ahi, alo, M * 128 / 4);
    wsplit_t<<<dim3(1024 / 32, 128 / 32), dim3(32, 8)>>>(W3, wthi, wtlo, 128, 1024);
    gemm_mma_split<<<dim3(8, M / 128), 256>>>(ahi, alo, wthi, wtlo, b3, zx, M, 1024, 128);
    lstm_rec<256, 16, 8, 16, 1><<<128, 256>>>(zx, U3, bufA, flags + 2 * 8 * T_STEPS);

    // ---- Layer 4: F=256 -> H=256 (N=1024, K=256) ----
    split_bf16<<<M * 256 / 4 / 256, 256>>>(bufA, ahi, alo, M * 256 / 4);
    wsplit_t<<<dim3(1024 / 32, 256 / 32), dim3(32, 8)>>>(W4, wthi, wtlo, 256, 1024);
    gemm_mma_split<<<dim3(8, M / 128), 256>>>(ahi, alo, wthi, wtlo, b4, zx, M, 1024, 256);
    lstm_rec<256, 16, 8, 16, 1><<<128, 256>>>(zx, U4, out, flags + 3 * 8 * T_STEPS);
}